// round 2
// baseline (speedup 1.0000x reference)
#include <cuda_runtime.h>
#include <math.h>

#define BATCH 256
#define SEQ   512
#define DIN   64
#define HID   256

// Scratch (device globals; allocation APIs are forbidden)
__device__ float g_bufA[(size_t)BATCH * SEQ * HID];   // 128 MiB
__device__ float g_bufB[(size_t)BATCH * SEQ * HID];   // 128 MiB
__device__ float g_hfin[(size_t)BATCH * HID];

// ---------------------------------------------------------------------------
// helpers
// ---------------------------------------------------------------------------
__device__ __forceinline__ unsigned long long ffma2(unsigned long long a,
                                                    unsigned long long b,
                                                    unsigned long long c) {
    unsigned long long d;
    asm("fma.rn.f32x2 %0, %1, %2, %3;" : "=l"(d) : "l"(a), "l"(b), "l"(c));
    return d;
}
__device__ __forceinline__ float2 u2f(unsigned long long v) {
    float2 r;
    asm("mov.b64 {%0, %1}, %2;" : "=f"(r.x), "=f"(r.y) : "l"(v));
    return r;
}
__device__ __forceinline__ unsigned long long pack2(float a, float b) {
    unsigned long long r;
    asm("mov.b64 %0, {%1, %2};" : "=l"(r) : "f"(a), "f"(b));
    return r;
}
__device__ __forceinline__ float tanh_fast(float x) {
    float r;
    asm("tanh.approx.f32 %0, %1;" : "=f"(r) : "f"(x));
    return r;
}

// ---------------------------------------------------------------------------
// Recurrence v2: 128 blocks x 1024 threads, 2 batch rows per block.
// Thread t: op = t>>3 (output pair 2op,2op+1), ks = t&7 (k-slice of 32).
// Weights for out 2op in 16 u64 regs; for out 2op+1 in smem (8 ulonglong2).
// h double-buffered in smem with 36-float chunk skew (bank-conflict-free).
// Reduction over 8 k-slices via 3 shfl.xor rounds (ks = lane bits 0..2).
// ---------------------------------------------------------------------------
#define SMEM_W_BYTES  (8 * 1024 * 16)           // 128 KB: ulonglong2[8][1024]
#define H_ROW_STRIDE  288                       // 8 chunks * 36 floats
#define H_BUF_STRIDE  (2 * H_ROW_STRIDE)        // 576 floats per buffer
#define RNN_SMEM_TOTAL (SMEM_W_BYTES + 2 * H_BUF_STRIDE * 4)

__global__ __launch_bounds__(1024, 1) void rnn_recur2(
    const float* __restrict__ xp,      // [BATCH, SEQ, HID] (bias pre-added)
    const float* __restrict__ Whh,     // [HID, HID]
    float* __restrict__ out_seq,       // [BATCH, SEQ, HID] or null
    float* __restrict__ out_final)     // [BATCH, HID] or null
{
    extern __shared__ char smem_raw[];
    ulonglong2* wsm = reinterpret_cast<ulonglong2*>(smem_raw);       // [8][1024]
    float*      hbuf = reinterpret_cast<float*>(smem_raw + SMEM_W_BYTES);

    const int t  = threadIdx.x;
    const int op = t >> 3;          // 0..127
    const int ks = t & 7;           // 0..7
    const int o0 = op * 2;
    const int k0 = ks * 32;

    // out o0 weights -> registers (16 u64 = 32 floats)
    unsigned long long w0[16];
    {
        const ulonglong2* wr0 =
            reinterpret_cast<const ulonglong2*>(Whh + o0 * HID + k0);
#pragma unroll
        for (int j = 0; j < 8; j++) {
            ulonglong2 v = wr0[j];
            w0[2 * j]     = v.x;
            w0[2 * j + 1] = v.y;
        }
        // out o0+1 weights -> smem
        const ulonglong2* wr1 =
            reinterpret_cast<const ulonglong2*>(Whh + (o0 + 1) * HID + k0);
#pragma unroll
        for (int j = 0; j < 8; j++) wsm[j * 1024 + t] = wr1[j];
    }

    // zero initial h (both buffers' buffer 0 is enough, zero all for safety)
    for (int i = t; i < 2 * H_BUF_STRIDE; i += 1024) hbuf[i] = 0.0f;
    __syncthreads();

    // writer role: ks 0..3 -> (row, out) = (0,o0),(0,o0+1),(1,o0),(1,o0+1)
    const bool writer = (ks < 4);
    const int  wrow   = ks >> 1;
    const int  wo     = o0 + (ks & 1);
    const int  grow   = blockIdx.x * 2 + wrow;
    const float* myxp = xp + ((size_t)grow * SEQ) * HID + wo;
    float* myout = out_seq ? out_seq + ((size_t)grow * SEQ) * HID + wo
                           : (float*)0;
    const int wslot = wrow * H_ROW_STRIDE + (wo >> 5) * 36 + (wo & 31);

    const int hread0 = ks * 36;
    const int hread1 = H_ROW_STRIDE + ks * 36;

    int   buf   = 0;
    float hlast = 0.0f;

    for (int s = 0; s < SEQ; s++) {
        float xv = 0.0f;
        if (writer) xv = __ldg(myxp + (size_t)s * HID);

        const float* hb = hbuf + buf * H_BUF_STRIDE;
        const ulonglong2* h0 = reinterpret_cast<const ulonglong2*>(hb + hread0);
        const ulonglong2* h1 = reinterpret_cast<const ulonglong2*>(hb + hread1);

        unsigned long long a00 = 0ull, a01 = 0ull, a10 = 0ull, a11 = 0ull;
#pragma unroll
        for (int j = 0; j < 8; j++) {
            ulonglong2 hv0 = h0[j];
            ulonglong2 hv1 = h1[j];
            ulonglong2 wv  = wsm[j * 1024 + t];
            a00 = ffma2(w0[2 * j],     hv0.x, a00);
            a00 = ffma2(w0[2 * j + 1], hv0.y, a00);
            a01 = ffma2(wv.x,          hv0.x, a01);
            a01 = ffma2(wv.y,          hv0.y, a01);
            a10 = ffma2(w0[2 * j],     hv1.x, a10);
            a10 = ffma2(w0[2 * j + 1], hv1.y, a10);
            a11 = ffma2(wv.x,          hv1.x, a11);
            a11 = ffma2(wv.y,          hv1.y, a11);
        }
        float2 f;
        f = u2f(a00); float d00 = f.x + f.y;
        f = u2f(a01); float d01 = f.x + f.y;
        f = u2f(a10); float d10 = f.x + f.y;
        f = u2f(a11); float d11 = f.x + f.y;
#pragma unroll
        for (int m = 1; m < 8; m <<= 1) {
            d00 += __shfl_xor_sync(0xffffffffu, d00, m);
            d01 += __shfl_xor_sync(0xffffffffu, d01, m);
            d10 += __shfl_xor_sync(0xffffffffu, d10, m);
            d11 += __shfl_xor_sync(0xffffffffu, d11, m);
        }
        if (writer) {
            float d  = (ks == 0) ? d00 : (ks == 1) ? d01 : (ks == 2) ? d10 : d11;
            float hn = tanh_fast(d + xv);
            hlast = hn;
            hbuf[(buf ^ 1) * H_BUF_STRIDE + wslot] = hn;
            if (myout) myout[(size_t)s * HID] = hn;
        }
        __syncthreads();
        buf ^= 1;
    }
    if (out_final && writer) out_final[(size_t)grow * HID + wo] = hlast;
}

// ---------------------------------------------------------------------------
// GEMM v2: Y[M,256] = X[M,K] @ W[256,K]^T + (ba+bb)
// Block tile 128M x 128N, 256 threads, thread tile 8x8 (f32x2 accumulators).
// grid = (M/128, 2)
// ---------------------------------------------------------------------------
template <int K>
__global__ __launch_bounds__(256, 2) void gemm2(
    const float* __restrict__ X, const float* __restrict__ W,
    const float* __restrict__ ba, const float* __restrict__ bb,
    float* __restrict__ Y)
{
    __shared__ float xs[16][128];
    __shared__ float ws[16][128];
    const int t  = threadIdx.x;
    const int tx = t & 15;    // N: 16 x 8
    const int ty = t >> 4;    // M: 16 x 8
    const size_t m0 = (size_t)blockIdx.x * 128;
    const int    n0 = blockIdx.y * 128;

    unsigned long long acc[8][4];
#pragma unroll
    for (int mi = 0; mi < 8; mi++)
#pragma unroll
        for (int ni = 0; ni < 4; ni++) acc[mi][ni] = 0ull;

    const int r = t & 127;
    const float* src_base = (t < 128) ? (X + (m0 + r) * K)
                                      : (W + (size_t)(n0 + r) * K);
    float* dst_col = (t < 128) ? &xs[0][r] : &ws[0][r];

    for (int kc = 0; kc < K; kc += 16) {
        // stage one 16-wide K chunk (transposed into [k][row])
        const float4* src = reinterpret_cast<const float4*>(src_base + kc);
#pragma unroll
        for (int q = 0; q < 4; q++) {
            float4 v = src[q];
            dst_col[(4 * q + 0) * 128] = v.x;
            dst_col[(4 * q + 1) * 128] = v.y;
            dst_col[(4 * q + 2) * 128] = v.z;
            dst_col[(4 * q + 3) * 128] = v.w;
        }
        __syncthreads();

#pragma unroll
        for (int k = 0; k < 16; k++) {
            float4 a0 = *reinterpret_cast<const float4*>(&xs[k][ty * 8]);
            float4 a1 = *reinterpret_cast<const float4*>(&xs[k][ty * 8 + 4]);
            ulonglong2 b0 = *reinterpret_cast<const ulonglong2*>(&ws[k][tx * 8]);
            ulonglong2 b1 = *reinterpret_cast<const ulonglong2*>(&ws[k][tx * 8 + 4]);
            float am[8] = {a0.x, a0.y, a0.z, a0.w, a1.x, a1.y, a1.z, a1.w};
            unsigned long long bp0 = b0.x, bp1 = b0.y, bp2 = b1.x, bp3 = b1.y;
#pragma unroll
            for (int mi = 0; mi < 8; mi++) {
                unsigned long long am2 = pack2(am[mi], am[mi]);
                acc[mi][0] = ffma2(bp0, am2, acc[mi][0]);
                acc[mi][1] = ffma2(bp1, am2, acc[mi][1]);
                acc[mi][2] = ffma2(bp2, am2, acc[mi][2]);
                acc[mi][3] = ffma2(bp3, am2, acc[mi][3]);
            }
        }
        __syncthreads();
    }

    float bias[8];
#pragma unroll
    for (int i = 0; i < 8; i++)
        bias[i] = ba[n0 + tx * 8 + i] + bb[n0 + tx * 8 + i];

#pragma unroll
    for (int mi = 0; mi < 8; mi++) {
        float* yrow = Y + (m0 + ty * 8 + mi) * HID + n0 + tx * 8;
        float2 f0 = u2f(acc[mi][0]);
        float2 f1 = u2f(acc[mi][1]);
        float2 f2 = u2f(acc[mi][2]);
        float2 f3 = u2f(acc[mi][3]);
        float4 o0 = make_float4(f0.x + bias[0], f0.y + bias[1],
                                f1.x + bias[2], f1.y + bias[3]);
        float4 o1 = make_float4(f2.x + bias[4], f2.y + bias[5],
                                f3.x + bias[6], f3.y + bias[7]);
        reinterpret_cast<float4*>(yrow)[0] = o0;
        reinterpret_cast<float4*>(yrow)[1] = o1;
    }
}

// ---------------------------------------------------------------------------
// out[b] = sigmoid(h2[b,:] . Wfc + bfc)
// ---------------------------------------------------------------------------
__global__ void fc_sigmoid_kernel(const float* __restrict__ h2,
                                  const float* __restrict__ Wfc,
                                  const float* __restrict__ bfc,
                                  float* __restrict__ out)
{
    __shared__ float wf[HID];
    const int t = threadIdx.x;
    wf[t] = Wfc[t];
    __syncthreads();
    const float* hb = h2 + (size_t)t * HID;
    float s = 0.0f;
#pragma unroll 8
    for (int k = 0; k < HID; k++) s = fmaf(hb[k], wf[k], s);
    float z = s + bfc[0];
    out[t] = 1.0f / (1.0f + expf(-z));
}

// ---------------------------------------------------------------------------
// launch
// ---------------------------------------------------------------------------
extern "C" void kernel_launch(void* const* d_in, const int* in_sizes, int n_in,
                              void* d_out, int out_size)
{
    const float* x     = (const float*)d_in[0];
    const float* W_ih0 = (const float*)d_in[1];
    const float* W_hh0 = (const float*)d_in[2];
    const float* b_ih0 = (const float*)d_in[3];
    const float* b_hh0 = (const float*)d_in[4];
    const float* W_ih1 = (const float*)d_in[5];
    const float* W_hh1 = (const float*)d_in[6];
    const float* b_ih1 = (const float*)d_in[7];
    const float* b_hh1 = (const float*)d_in[8];
    const float* W_fc  = (const float*)d_in[9];
    const float* b_fc  = (const float*)d_in[10];
    float* out = (float*)d_out;

    float *bufA, *bufB, *hfin;
    cudaGetSymbolAddress((void**)&bufA, g_bufA);
    cudaGetSymbolAddress((void**)&bufB, g_bufB);
    cudaGetSymbolAddress((void**)&hfin, g_hfin);

    cudaFuncSetAttribute(rnn_recur2,
                         cudaFuncAttributeMaxDynamicSharedMemorySize,
                         RNN_SMEM_TOTAL);

    const dim3 ggrid((BATCH * SEQ) / 128, 2);

    // A: xp0 = x @ W_ih0^T + (b_ih0 + b_hh0)
    gemm2<DIN><<<ggrid, 256>>>(x, W_ih0, b_ih0, b_hh0, bufA);
    // B: layer-0 recurrence -> h1 sequence
    rnn_recur2<<<BATCH / 2, 1024, RNN_SMEM_TOTAL>>>(bufA, W_hh0, bufB,
                                                    (float*)0);
    // C: xp1 = h1 @ W_ih1^T + (b_ih1 + b_hh1)
    gemm2<HID><<<ggrid, 256>>>(bufB, W_ih1, b_ih1, b_hh1, bufA);
    // D: layer-1 recurrence -> final hidden only
    rnn_recur2<<<BATCH / 2, 1024, RNN_SMEM_TOTAL>>>(bufA, W_hh1, (float*)0,
                                                    hfin);
    // E: fc + sigmoid
    fc_sigmoid_kernel<<<1, HID>>>(hfin, W_fc, b_fc, out);
}